// round 16
// baseline (speedup 1.0000x reference)
#include <cuda_runtime.h>
#include <cuda_fp16.h>
#include <cstddef>

#define EPSF 1e-6f
#define LAMBDAF 0.01f

// Problem constants (fixed shapes)
//  x: (4,16,16,16,16)  a: (4,16,16,16,1)  w: (144,32,4,4)
//  out: p_out (4,14,14,32,16) ++ a_out (4,14,14,32,1)
#define NCAP 144
#define CCAP 32
#define NPOS 784           // 4*14*14
#define POUT_ELEMS 401408  // 784*32*16
#define WHALF_ELEMS (NCAP * CCAP * 16)  // 73728 halves = 144KB
#define VC_BYTES_PER_POS (NCAP * CCAP * 16 * 2)  // 147456 B per position
#define NT 128             // threads per CTA (4 warps = 1 position)

// fp16 weight staging buffer, layout [n][k2][c][8]:
//   wh[((n*2+k2)*32 + c)*8 + j] = w[n][c][ k2*8 + j ]
__device__ __half g_wh[WHALF_ELEMS];

// fp16 vote cache: votes are identical across EM passes (depend only on pose/W),
// so pass0 computes them once and passE re-reads instead of recomputing.
// Layout [pid][n][p2][c][8halves]: byte addr = pid*147456 + n*1024 + p2*512 + c*16.
__device__ __half g_vc[(size_t)NPOS * NCAP * CCAP * 16];

// One thread produces one uint4 (8 halves) from two float4 loads.
__global__ void convert_w_kernel(const float* __restrict__ w) {
    int q = blockIdx.x * 256 + threadIdx.x;  // 0..9215
    if (q >= WHALF_ELEMS / 8) return;
    int c = q & 31;
    int k2 = (q >> 5) & 1;
    int n = q >> 6;
    const float4* src = reinterpret_cast<const float4*>(w + ((n * 32 + c) << 4) + k2 * 8);
    float4 f0 = __ldg(src + 0), f1 = __ldg(src + 1);
    __half2 h[4];
    h[0] = __floats2half2_rn(f0.x, f0.y);
    h[1] = __floats2half2_rn(f0.z, f0.w);
    h[2] = __floats2half2_rn(f1.x, f1.y);
    h[3] = __floats2half2_rn(f1.z, f1.w);
    reinterpret_cast<uint4*>(g_wh)[q] = *reinterpret_cast<uint4*>(h);
}

__device__ __forceinline__ float warp_max(float v) {
#pragma unroll
    for (int o = 16; o; o >>= 1) v = fmaxf(v, __shfl_xor_sync(0xffffffffu, v, o));
    return v;
}

struct Smem {
    float pose[2304];   // [n*16 + p], pose patch (64B rows -> float4 broadcast loads)
    float a[144];       // a_in per n
    float WS[4 * 548];  // per-warp reduction staging (stride-17 padded), 4 warps
    float M1[640];      // S1 (sum r*v) then mu, in place  [c*20+p] (float4 pad)
    float M2[640];      // I2S = 1/(2 sigma^2)             [c*20+p]
    float BB[640];      // -2 * I2S * mu                   [c*20+p]
    float RSB[4 * 33];  // per-warp rsum staging
    float RS[32];       // r_sum per c
    float Lc[32];       // log(a_out+eps) - SH[c] - CC[c]
    float AO[32];       // a_out per c
};

// Compute 16 votes for capsule n given its weight base pointer
// (weights fp16; pose via 4x LDS.128 broadcast).
__device__ __forceinline__ void votes16p(const Smem& sm, const char* wptr, int n, float* v) {
    uint4 ua = *reinterpret_cast<const uint4*>(wptr);        // rows j=0,1
    uint4 ub = *reinterpret_cast<const uint4*>(wptr + 512);  // rows j=2,3
    const __half2* ha = reinterpret_cast<const __half2*>(&ua);
    const __half2* hb = reinterpret_cast<const __half2*>(&ub);
    float w0[4], w1[4], w2[4], w3[4];
    float2 t;
    t = __half22float2(ha[0]); w0[0] = t.x; w0[1] = t.y;
    t = __half22float2(ha[1]); w0[2] = t.x; w0[3] = t.y;
    t = __half22float2(ha[2]); w1[0] = t.x; w1[1] = t.y;
    t = __half22float2(ha[3]); w1[2] = t.x; w1[3] = t.y;
    t = __half22float2(hb[0]); w2[0] = t.x; w2[1] = t.y;
    t = __half22float2(hb[1]); w2[2] = t.x; w2[3] = t.y;
    t = __half22float2(hb[2]); w3[0] = t.x; w3[1] = t.y;
    t = __half22float2(hb[3]); w3[2] = t.x; w3[3] = t.y;
    const float4* ps4 = reinterpret_cast<const float4*>(sm.pose + n * 16);
#pragma unroll
    for (int i = 0; i < 4; i++) {
        float4 pp = ps4[i];  // (p0,p1,p2,p3) of row i, one LDS.128 broadcast
#pragma unroll
        for (int k = 0; k < 4; k++)
            v[4 * i + k] = fmaf(pp.x, w0[k], fmaf(pp.y, w1[k], fmaf(pp.z, w2[k], pp.w * w3[k])));
    }
}

// Unpack a cached vote pair (2 uint4 = 16 halves) to fp32.
__device__ __forceinline__ void unpack16(uint4 s0, uint4 s1, float* v) {
    const __half2* h0 = reinterpret_cast<const __half2*>(&s0);
    const __half2* h1 = reinterpret_cast<const __half2*>(&s1);
    float2 t;
#pragma unroll
    for (int i = 0; i < 4; i++) {
        t = __half22float2(h0[i]); v[2 * i] = t.x; v[2 * i + 1] = t.y;
        t = __half22float2(h1[i]); v[8 + 2 * i] = t.x; v[8 + 2 * i + 1] = t.y;
    }
}

// Mahalanobis sum with TWO 8-deep partial chains (halves exposed FMA latency).
__device__ __forceinline__ float ds16(const float* A, const float* Bv, const float* v) {
    float d0 = 0.f, d1 = 0.f;
#pragma unroll
    for (int i = 0; i < 2; i++) {
#pragma unroll
        for (int k = 0; k < 4; k++) {
            int pa = 8 * i + k, pb = 8 * i + 4 + k;
            float ta = fmaf(A[pa], v[pa], Bv[pa]);
            d0 = fmaf(ta, v[pa], d0);
            float tb = fmaf(A[pb], v[pb], Bv[pb]);
            d1 = fmaf(tb, v[pb], d1);
        }
    }
    return d0 + d1;
}

// Shared epilogue of a vote pass: stage + reduce T1/rsum into M1/RS, stage T2.
// 4-warp staging (half the LDS of the 8-warp version).
__device__ __forceinline__ void pass_reduce(Smem& sm, const float* T1, const float* T2,
                                            float rsum, int lane, int g, int tid) {
#pragma unroll
    for (int p = 0; p < 16; p++) sm.WS[g * 548 + lane * 17 + p] = T1[p];
    sm.RSB[g * 33 + lane] = rsum;
    __syncthreads();
    for (int q = tid; q < 512; q += NT) {
        int c = q >> 4, p = q & 15;
        float s = 0.f;
#pragma unroll
        for (int gg = 0; gg < 4; gg++) s += sm.WS[gg * 548 + c * 17 + p];
        sm.M1[c * 20 + p] = s;
    }
    if (tid < 32) {
        float s = 0.f;
#pragma unroll
        for (int gg = 0; gg < 4; gg++) s += sm.RSB[gg * 33 + tid];
        sm.RS[tid] = s;
    }
    __syncthreads();
#pragma unroll
    for (int p = 0; p < 16; p++) sm.WS[g * 548 + lane * 17 + p] = T2[p];
    __syncthreads();
}

// Pass 0: uniform responsibilities r0 = a_n / C; also fills the vote cache.
// 4 warps/position: warp g handles n = g, g+4, ... (36 capsules).
__device__ __forceinline__ void vote_pass0(Smem& sm, char* vcp, int lane, int g, int tid) {
    const char* wptr = reinterpret_cast<const char*>(g_wh) + (g << 10) + (lane << 4);
    vcp += (g << 10) + (lane << 4);
    float T1[16], T2[16];
#pragma unroll
    for (int p = 0; p < 16; p++) { T1[p] = 0.f; T2[p] = 0.f; }
    float rsum = 0.f;
#pragma unroll 2
    for (int n = g; n < NCAP; n += 4, wptr += 4096, vcp += 4096) {
        float v[16];
        votes16p(sm, wptr, n, v);
        // store votes to the L2-resident cache (coalesced STG.128 x2, imm offsets)
        uint4 s0, s1;
        __half2* h0 = reinterpret_cast<__half2*>(&s0);
        __half2* h1 = reinterpret_cast<__half2*>(&s1);
#pragma unroll
        for (int i = 0; i < 4; i++) {
            h0[i] = __floats2half2_rn(v[2 * i], v[2 * i + 1]);
            h1[i] = __floats2half2_rn(v[8 + 2 * i], v[8 + 2 * i + 1]);
        }
        *reinterpret_cast<uint4*>(vcp) = s0;
        *reinterpret_cast<uint4*>(vcp + 512) = s1;
        float rn = sm.a[n] * (1.0f / 32.0f);
        rsum += rn;
#pragma unroll
        for (int p = 0; p < 16; p++) {
            float rv = rn * v[p];
            T1[p] += rv;
            T2[p] = fmaf(rv, v[p], T2[p]);
        }
    }
    pass_reduce(sm, T1, T2, rsum, lane, g, tid);
}

// E+M pass: fused E-step (warp softmax over c=lane) + next M accumulation.
// Votes from the fp16 cache; pair (n, n+4) per step with interleaved shuffle
// chains; next pair software-prefetched so L2 latency hides under the chain.
__device__ __forceinline__ void vote_passE(Smem& sm, const char* vcp, int lane, int g, int tid) {
    float A[16], Bv[16];
    {
        const float4* A4p = reinterpret_cast<const float4*>(sm.M2 + lane * 20);
        const float4* B4p = reinterpret_cast<const float4*>(sm.BB + lane * 20);
#pragma unroll
        for (int i = 0; i < 4; i++) {
            float4 a4 = A4p[i], b4 = B4p[i];
            A[4 * i + 0] = a4.x; A[4 * i + 1] = a4.y; A[4 * i + 2] = a4.z; A[4 * i + 3] = a4.w;
            Bv[4 * i + 0] = b4.x; Bv[4 * i + 1] = b4.y; Bv[4 * i + 2] = b4.z; Bv[4 * i + 3] = b4.w;
        }
    }
    float Lrm;
    {
        float Lr2 = sm.Lc[lane];
        Lrm = Lr2 - warp_max(Lr2);  // shift folded in: ln' = Lrm - ds  (<= 0)
    }
    float T1[16], T2[16];
#pragma unroll
    for (int p = 0; p < 16; p++) { T1[p] = 0.f; T2[p] = 0.f; }
    float rsum = 0.f;

    vcp += (g << 10) + (lane << 4);
    // prefetch pair 0: streams at +0, +512 (p2=1), +4096 (n+4), +4608
    uint4 c0 = *reinterpret_cast<const uint4*>(vcp);
    uint4 c1 = *reinterpret_cast<const uint4*>(vcp + 512);
    uint4 c2 = *reinterpret_cast<const uint4*>(vcp + 4096);
    uint4 c3 = *reinterpret_cast<const uint4*>(vcp + 4608);
    vcp += 8192;

#pragma unroll 1
    for (int i = 0; i < 18; i++, vcp += 8192) {  // 18 pairs (n, n+4)
        int n = g + i * 8;
        // prefetch next pair before consuming this one (hides L2 latency)
        uint4 d0, d1, d2, d3;
        if (i < 17) {
            d0 = *reinterpret_cast<const uint4*>(vcp);
            d1 = *reinterpret_cast<const uint4*>(vcp + 512);
            d2 = *reinterpret_cast<const uint4*>(vcp + 4096);
            d3 = *reinterpret_cast<const uint4*>(vcp + 4608);
        }
        float vA[16], vB[16];
        unpack16(c0, c1, vA);
        float dsA = ds16(A, Bv, vA);  // two 8-deep chains
        float eA = __expf(Lrm - dsA);
        unpack16(c2, c3, vB);
        float dsB = ds16(A, Bv, vB);
        float eB = __expf(Lrm - dsB);
        // interleaved butterfly sums over the 32 lanes (softmax over c)
        float seA = eA, seB = eB;
#pragma unroll
        for (int o = 16; o; o >>= 1) {
            seA += __shfl_xor_sync(0xffffffffu, seA, o);
            seB += __shfl_xor_sync(0xffffffffu, seB, o);
        }
        // branchless guard (never binds on real data; keeps one basic block)
        seA = fmaxf(seA, 1e-30f);
        seB = fmaxf(seB, 1e-30f);
        float rnA = sm.a[n] * __fdividef(eA, seA);
        float rnB = sm.a[n + 4] * __fdividef(eB, seB);
        rsum += rnA + rnB;
#pragma unroll
        for (int p = 0; p < 16; p++) {
            float rvA = rnA * vA[p];
            float rvB = rnB * vB[p];
            T1[p] += rvA + rvB;
            T2[p] = fmaf(rvA, vA[p], fmaf(rvB, vB[p], T2[p]));
        }
        c0 = d0; c1 = d1; c2 = d2; c3 = d3;
    }
    pass_reduce(sm, T1, T2, rsum, lane, g, tid);
}

// M-step statistics. Finishes the T2 reduction (staged in WS), writes mu/I2S/BB.
// Per-c reductions of 0.5*log(sig) and i2s*mu^2 go through each thread's OWN
// already-consumed WS slots (gg=0/gg=1), finished by warp0 after the barrier.
__device__ __forceinline__ void stats(Smem& sm, const float* __restrict__ bu,
                                      const float* __restrict__ ba, int tid) {
    for (int q = tid; q < 512; q += NT) {
        int c = q >> 4, p = q & 15, qi = c * 20 + p;
        float s2 = 0.f;
#pragma unroll
        for (int gg = 0; gg < 4; gg++) s2 += sm.WS[gg * 548 + c * 17 + p];
        float rs = sm.RS[c];
        float inv = __fdividef(1.0f, rs + EPSF);
        float mu = sm.M1[qi] * inv;
        // sigma^2 = S2/(rs+eps) - mu^2 * (2 - rs/(rs+eps)) + eps
        float sig = fmaf(-mu * mu, 2.0f - rs * inv, s2 * inv) + EPSF;
        float i2s = __fdividef(0.5f, sig);
        sm.M1[qi] = mu;  // in place: S1 -> mu
        sm.M2[qi] = i2s;
        sm.BB[qi] = -2.0f * i2s * mu;
        sm.WS[c * 17 + p] = 0.5f * __logf(sig);   // own gg=0 slot (post-read)
        sm.WS[548 + c * 17 + p] = i2s * mu * mu;  // own gg=1 slot (post-read)
    }
    __syncthreads();
    if (tid < 32) {
        int c = tid;
        float sumh = 0.f, cc = 0.f;
#pragma unroll
        for (int p = 0; p < 16; p++) {  // stride-17 rows: conflict-free across c
            sumh += sm.WS[c * 17 + p];
            cc += sm.WS[548 + c * 17 + p];
        }
        float cost = (16.0f * bu[c] + sumh) * sm.RS[c];
        float logit = LAMBDAF * (ba[c] - cost);
        float ao = __fdividef(1.0f, 1.0f + __expf(-logit));
        sm.AO[c] = ao;
        sm.Lc[c] = __logf(ao + EPSF) - sumh - cc;  // C folded in
    }
    __syncthreads();
}

__global__ __launch_bounds__(NT, 4) void convcaps_kernel(
    const float* __restrict__ x, const float* __restrict__ a,
    const float* __restrict__ bu, const float* __restrict__ ba,
    const int* __restrict__ itp, float* __restrict__ out) {
    __shared__ Smem sm;
    int tid = threadIdx.x, lane = tid & 31, g = tid >> 5;
    int pid = blockIdx.x;
    int b = pid / 196;
    int rem = pid - b * 196;
    int oy = rem / 14;
    int ox = rem - oy * 14;
    char* vcp = reinterpret_cast<char*>(g_vc) + (size_t)pid * VC_BYTES_PER_POS;

    // Patch gather (float4-vectorized): n = (ki*3+kj)*16 + bc
    for (int q = tid; q < 576; q += NT) {
        int n = q >> 2, f = q & 3;
        int bc = n & 15, kk = n >> 4;
        int ki = kk / 3, kj = kk - ki * 3;
        const float4* src = reinterpret_cast<const float4*>(
            x + (((size_t)(b * 16 + oy + ki) * 16 + (ox + kj)) * 16 + bc) * 16);
        reinterpret_cast<float4*>(sm.pose)[q] = __ldg(src + f);
    }
    for (int n = tid; n < NCAP; n += NT) {
        int bc = n & 15, kk = n >> 4;
        int ki = kk / 3, kj = kk - ki * 3;
        sm.a[n] = a[((size_t)(b * 16 + oy + ki) * 16 + (ox + kj)) * 16 + bc];
    }
    __syncthreads();

    int iters = 2;
    if (itp) {
        int iv = __ldg(itp);
        if (iv >= 1 && iv <= 64) {
            iters = iv;
        } else {
            float f = __int_as_float(iv);  // guard against float-encoded scalar
            if (f >= 1.0f && f <= 64.0f) iters = (int)f;
        }
    }

    // iteration 0: uniform responsibilities (also fills the vote cache)
    vote_pass0(sm, vcp, lane, g, tid);
    stats(sm, bu, ba, tid);
    // iterations 1..iters-1: fused E-step (of prev iter) + M-accumulation
    for (int it = 1; it < iters; ++it) {
        vote_passE(sm, vcp, lane, g, tid);
        stats(sm, bu, ba, tid);
    }

    // outputs: p_out (pid*512 + c*16+p) then a_out (POUT_ELEMS + pid*32 + c)
    float* pout = out + (size_t)pid * 512;
    for (int q = tid; q < 512; q += NT) {
        int c = q >> 4, p = q & 15;
        pout[q] = sm.M1[c * 20 + p];
    }
    if (tid < 32) out[POUT_ELEMS + pid * 32 + tid] = sm.AO[tid];
}

extern "C" void kernel_launch(void* const* d_in, const int* in_sizes, int n_in,
                              void* d_out, int out_size) {
    const float* x = (const float*)d_in[0];
    const float* a = (const float*)d_in[1];
    const float* w = (const float*)d_in[2];
    const float* bu = (const float*)d_in[3];
    const float* ba = (const float*)d_in[4];
    const int* itp = (n_in >= 6) ? (const int*)d_in[5] : nullptr;
    convert_w_kernel<<<(WHALF_ELEMS / 8 + 255) / 256, 256>>>(w);
    convcaps_kernel<<<NPOS, NT>>>(x, a, bu, ba, itp, (float*)d_out);
}

// round 17
// speedup vs baseline: 1.1260x; 1.1260x over previous
#include <cuda_runtime.h>
#include <cuda_fp16.h>
#include <cstddef>

#define EPSF 1e-6f
#define LAMBDAF 0.01f

// Problem constants (fixed shapes)
//  x: (4,16,16,16,16)  a: (4,16,16,16,1)  w: (144,32,4,4)
//  out: p_out (4,14,14,32,16) ++ a_out (4,14,14,32,1)
#define NCAP 144
#define CCAP 32
#define NPOS 784           // 4*14*14
#define POUT_ELEMS 401408  // 784*32*16
#define WHALF_ELEMS (NCAP * CCAP * 16)  // 73728 halves = 144KB (L1-resident @ 2 CTA)
#define VC_BYTES_PER_POS (NCAP * CCAP * 16 * 2)  // 147456 B per position

// fp16 weight staging buffer, layout [n][k2][c][8]:
//   wh[((n*2+k2)*32 + c)*8 + j] = w[n][c][ k2*8 + j ]
__device__ __half g_wh[WHALF_ELEMS];

// fp16 vote cache: votes are identical across EM passes (depend only on pose/W),
// so pass0 computes them once and passE re-reads instead of recomputing.
// Layout [pid][n][p2][c][8halves]: byte addr = pid*147456 + n*1024 + p2*512 + c*16.
__device__ __half g_vc[(size_t)NPOS * NCAP * CCAP * 16];

// One thread produces one uint4 (8 halves) from two float4 loads.
__global__ void convert_w_kernel(const float* __restrict__ w) {
    int q = blockIdx.x * 256 + threadIdx.x;  // 0..9215
    if (q >= WHALF_ELEMS / 8) return;
    int c = q & 31;
    int k2 = (q >> 5) & 1;
    int n = q >> 6;
    const float4* src = reinterpret_cast<const float4*>(w + ((n * 32 + c) << 4) + k2 * 8);
    float4 f0 = __ldg(src + 0), f1 = __ldg(src + 1);
    __half2 h[4];
    h[0] = __floats2half2_rn(f0.x, f0.y);
    h[1] = __floats2half2_rn(f0.z, f0.w);
    h[2] = __floats2half2_rn(f1.x, f1.y);
    h[3] = __floats2half2_rn(f1.z, f1.w);
    reinterpret_cast<uint4*>(g_wh)[q] = *reinterpret_cast<uint4*>(h);
}

__device__ __forceinline__ float warp_max(float v) {
#pragma unroll
    for (int o = 16; o; o >>= 1) v = fmaxf(v, __shfl_xor_sync(0xffffffffu, v, o));
    return v;
}

struct Smem {
    float pose[2304];   // [n*16 + p], pose patch (64B rows -> float4 broadcast loads)
    float a[144];       // a_in per n
    float WS[8 * 548];  // per-warp reduction staging (stride-17 padded)
    float M1[640];      // S1 (sum r*v) then mu, in place  [c*20+p] (float4 pad)
    float M2[640];      // I2S = 1/(2 sigma^2)             [c*20+p]
    float BB[640];      // -2 * I2S * mu                   [c*20+p]
    float RSB[8 * 33];  // per-warp rsum staging
    float RS[32];       // r_sum per c
    float Lc[32];       // log(a_out+eps) - SH[c] - CC[c]
    float AO[32];       // a_out per c
};

// Compute 16 votes for capsule n given its weight base pointer
// (weights fp16, L1-resident; pose via 4x LDS.128 broadcast).
__device__ __forceinline__ void votes16p(const Smem& sm, const char* wptr, int n, float* v) {
    uint4 ua = *reinterpret_cast<const uint4*>(wptr);        // rows j=0,1
    uint4 ub = *reinterpret_cast<const uint4*>(wptr + 512);  // rows j=2,3
    const __half2* ha = reinterpret_cast<const __half2*>(&ua);
    const __half2* hb = reinterpret_cast<const __half2*>(&ub);
    float w0[4], w1[4], w2[4], w3[4];
    float2 t;
    t = __half22float2(ha[0]); w0[0] = t.x; w0[1] = t.y;
    t = __half22float2(ha[1]); w0[2] = t.x; w0[3] = t.y;
    t = __half22float2(ha[2]); w1[0] = t.x; w1[1] = t.y;
    t = __half22float2(ha[3]); w1[2] = t.x; w1[3] = t.y;
    t = __half22float2(hb[0]); w2[0] = t.x; w2[1] = t.y;
    t = __half22float2(hb[1]); w2[2] = t.x; w2[3] = t.y;
    t = __half22float2(hb[2]); w3[0] = t.x; w3[1] = t.y;
    t = __half22float2(hb[3]); w3[2] = t.x; w3[3] = t.y;
    const float4* ps4 = reinterpret_cast<const float4*>(sm.pose + n * 16);
#pragma unroll
    for (int i = 0; i < 4; i++) {
        float4 pp = ps4[i];  // (p0,p1,p2,p3) of row i, one LDS.128 broadcast
#pragma unroll
        for (int k = 0; k < 4; k++)
            v[4 * i + k] = fmaf(pp.x, w0[k], fmaf(pp.y, w1[k], fmaf(pp.z, w2[k], pp.w * w3[k])));
    }
}

// Unpack a cached vote pair (2 uint4 = 16 halves) to fp32.
__device__ __forceinline__ void unpack16(uint4 s0, uint4 s1, float* v) {
    const __half2* h0 = reinterpret_cast<const __half2*>(&s0);
    const __half2* h1 = reinterpret_cast<const __half2*>(&s1);
    float2 t;
#pragma unroll
    for (int i = 0; i < 4; i++) {
        t = __half22float2(h0[i]); v[2 * i] = t.x; v[2 * i + 1] = t.y;
        t = __half22float2(h1[i]); v[8 + 2 * i] = t.x; v[8 + 2 * i + 1] = t.y;
    }
}

// Mahalanobis sum with TWO 8-deep partial chains (halves exposed FMA latency).
__device__ __forceinline__ float ds16(const float* A, const float* Bv, const float* v) {
    float d0 = 0.f, d1 = 0.f;
#pragma unroll
    for (int i = 0; i < 2; i++) {
#pragma unroll
        for (int k = 0; k < 4; k++) {
            int pa = 8 * i + k, pb = 8 * i + 4 + k;
            float ta = fmaf(A[pa], v[pa], Bv[pa]);
            d0 = fmaf(ta, v[pa], d0);
            float tb = fmaf(A[pb], v[pb], Bv[pb]);
            d1 = fmaf(tb, v[pb], d1);
        }
    }
    return d0 + d1;
}

// Shared epilogue of a vote pass: stage + reduce T1/rsum into M1/RS, stage T2.
// (T2's reduction is merged into stats() to save one barrier.)
__device__ __forceinline__ void pass_reduce(Smem& sm, const float* T1, const float* T2,
                                            float rsum, int lane, int g, int tid) {
#pragma unroll
    for (int p = 0; p < 16; p++) sm.WS[g * 548 + lane * 17 + p] = T1[p];
    sm.RSB[g * 33 + lane] = rsum;
    __syncthreads();
    for (int q = tid; q < 512; q += 256) {
        int c = q >> 4, p = q & 15;
        float s = 0.f;
#pragma unroll
        for (int gg = 0; gg < 8; gg++) s += sm.WS[gg * 548 + c * 17 + p];
        sm.M1[c * 20 + p] = s;
    }
    if (tid < 32) {
        float s = 0.f;
#pragma unroll
        for (int gg = 0; gg < 8; gg++) s += sm.RSB[gg * 33 + tid];
        sm.RS[tid] = s;
    }
    __syncthreads();
#pragma unroll
    for (int p = 0; p < 16; p++) sm.WS[g * 548 + lane * 17 + p] = T2[p];
    __syncthreads();
}

// Pass 0: uniform responsibilities r0 = a_n / C; also fills the vote cache.
__device__ __forceinline__ void vote_pass0(Smem& sm, char* vcp, int lane, int g, int tid) {
    const char* wptr = reinterpret_cast<const char*>(g_wh) + (g << 10) + (lane << 4);
    vcp += (g << 10) + (lane << 4);
    float T1[16], T2[16];
#pragma unroll
    for (int p = 0; p < 16; p++) { T1[p] = 0.f; T2[p] = 0.f; }
    float rsum = 0.f;
#pragma unroll 2
    for (int n = g; n < NCAP; n += 8, wptr += 8192, vcp += 8192) {
        float v[16];
        votes16p(sm, wptr, n, v);
        // store votes to the L2-resident cache (coalesced STG.128 x2, imm offsets)
        uint4 s0, s1;
        __half2* h0 = reinterpret_cast<__half2*>(&s0);
        __half2* h1 = reinterpret_cast<__half2*>(&s1);
#pragma unroll
        for (int i = 0; i < 4; i++) {
            h0[i] = __floats2half2_rn(v[2 * i], v[2 * i + 1]);
            h1[i] = __floats2half2_rn(v[8 + 2 * i], v[8 + 2 * i + 1]);
        }
        *reinterpret_cast<uint4*>(vcp) = s0;
        *reinterpret_cast<uint4*>(vcp + 512) = s1;
        float rn = sm.a[n] * (1.0f / 32.0f);
        rsum += rn;
#pragma unroll
        for (int p = 0; p < 16; p++) {
            float rv = rn * v[p];
            T1[p] += rv;
            T2[p] = fmaf(rv, v[p], T2[p]);
        }
    }
    pass_reduce(sm, T1, T2, rsum, lane, g, tid);
}

// E+M pass: fused E-step (warp softmax over c=lane) + next M accumulation.
// Votes from the fp16 cache; pair (n, n+8) per step with interleaved shuffle
// chains; next pair software-prefetched so L2 latency hides under the chain.
__device__ __forceinline__ void vote_passE(Smem& sm, const char* vcp, int lane, int g, int tid) {
    float A[16], Bv[16];
    {
        const float4* A4p = reinterpret_cast<const float4*>(sm.M2 + lane * 20);
        const float4* B4p = reinterpret_cast<const float4*>(sm.BB + lane * 20);
#pragma unroll
        for (int i = 0; i < 4; i++) {
            float4 a4 = A4p[i], b4 = B4p[i];
            A[4 * i + 0] = a4.x; A[4 * i + 1] = a4.y; A[4 * i + 2] = a4.z; A[4 * i + 3] = a4.w;
            Bv[4 * i + 0] = b4.x; Bv[4 * i + 1] = b4.y; Bv[4 * i + 2] = b4.z; Bv[4 * i + 3] = b4.w;
        }
    }
    float Lrm;
    {
        float Lr2 = sm.Lc[lane];
        Lrm = Lr2 - warp_max(Lr2);  // shift folded in: ln' = Lrm - ds  (<= 0)
    }
    float T1[16], T2[16];
#pragma unroll
    for (int p = 0; p < 16; p++) { T1[p] = 0.f; T2[p] = 0.f; }
    float rsum = 0.f;

    vcp += (g << 10) + (lane << 4);
    // prefetch pair 0: streams at +0, +512 (p2=1), +8192 (n+8), +8704
    uint4 c0 = *reinterpret_cast<const uint4*>(vcp);
    uint4 c1 = *reinterpret_cast<const uint4*>(vcp + 512);
    uint4 c2 = *reinterpret_cast<const uint4*>(vcp + 8192);
    uint4 c3 = *reinterpret_cast<const uint4*>(vcp + 8704);
    vcp += 16384;

#pragma unroll 1
    for (int i = 0; i < 9; i++, vcp += 16384) {  // 9 pairs (n, n+8)
        int n = g + i * 16;
        // prefetch next pair before consuming this one (hides L2 latency)
        uint4 d0, d1, d2, d3;
        if (i < 8) {
            d0 = *reinterpret_cast<const uint4*>(vcp);
            d1 = *reinterpret_cast<const uint4*>(vcp + 512);
            d2 = *reinterpret_cast<const uint4*>(vcp + 8192);
            d3 = *reinterpret_cast<const uint4*>(vcp + 8704);
        }
        float vA[16], vB[16];
        unpack16(c0, c1, vA);
        float dsA = ds16(A, Bv, vA);  // two 8-deep chains
        float eA = __expf(Lrm - dsA);
        unpack16(c2, c3, vB);
        float dsB = ds16(A, Bv, vB);
        float eB = __expf(Lrm - dsB);
        // interleaved butterfly sums over the 32 lanes (softmax over c)
        float seA = eA, seB = eB;
#pragma unroll
        for (int o = 16; o; o >>= 1) {
            seA += __shfl_xor_sync(0xffffffffu, seA, o);
            seB += __shfl_xor_sync(0xffffffffu, seB, o);
        }
        // branchless guard (never binds on real data; keeps one basic block)
        seA = fmaxf(seA, 1e-30f);
        seB = fmaxf(seB, 1e-30f);
        float rnA = sm.a[n] * __fdividef(eA, seA);
        float rnB = sm.a[n + 8] * __fdividef(eB, seB);
        rsum += rnA + rnB;
#pragma unroll
        for (int p = 0; p < 16; p++) {
            float rvA = rnA * vA[p];
            float rvB = rnB * vB[p];
            T1[p] += rvA + rvB;
            T2[p] = fmaf(rvA, vA[p], fmaf(rvB, vB[p], T2[p]));
        }
        c0 = d0; c1 = d1; c2 = d2; c3 = d3;
    }
    pass_reduce(sm, T1, T2, rsum, lane, g, tid);
}

// M-step statistics. Finishes the T2 reduction (staged in WS), writes mu, and
// (when another E-pass follows) I2S/BB/Lc. FINAL skips everything not needed
// for the outputs (mu, a_out): no I2S/BB stores, no cc reduction, no Lc.
template <bool FINAL>
__device__ __forceinline__ void stats(Smem& sm, const float* __restrict__ bu,
                                      const float* __restrict__ ba, int tid) {
    for (int q = tid; q < 512; q += 256) {
        int c = q >> 4, p = q & 15, qi = c * 20 + p;
        float s2 = 0.f;
#pragma unroll
        for (int gg = 0; gg < 8; gg++) s2 += sm.WS[gg * 548 + c * 17 + p];
        float rs = sm.RS[c];
        float inv = __fdividef(1.0f, rs + EPSF);
        float mu = sm.M1[qi] * inv;
        // sigma^2 = S2/(rs+eps) - mu^2 * (2 - rs/(rs+eps)) + eps
        float sig = fmaf(-mu * mu, 2.0f - rs * inv, s2 * inv) + EPSF;
        sm.M1[qi] = mu;  // in place: S1 -> mu
        sm.WS[c * 17 + p] = 0.5f * __logf(sig);  // own gg=0 slot (post-read)
        if (!FINAL) {
            float i2s = __fdividef(0.5f, sig);
            sm.M2[qi] = i2s;
            sm.BB[qi] = -2.0f * i2s * mu;
            sm.WS[548 + c * 17 + p] = i2s * mu * mu;  // own gg=1 slot (post-read)
        }
    }
    __syncthreads();
    if (tid < 32) {
        int c = tid;
        float sumh = 0.f;
#pragma unroll
        for (int p = 0; p < 16; p++) sumh += sm.WS[c * 17 + p];  // stride-17: conflict-free
        float cost = (16.0f * bu[c] + sumh) * sm.RS[c];
        float logit = LAMBDAF * (ba[c] - cost);
        float ao = __fdividef(1.0f, 1.0f + __expf(-logit));
        sm.AO[c] = ao;
        if (!FINAL) {
            float cc = 0.f;
#pragma unroll
            for (int p = 0; p < 16; p++) cc += sm.WS[548 + c * 17 + p];
            sm.Lc[c] = __logf(ao + EPSF) - sumh - cc;  // C folded in
        }
    }
    __syncthreads();
}

__global__ __launch_bounds__(256, 2) void convcaps_kernel(
    const float* __restrict__ x, const float* __restrict__ a,
    const float* __restrict__ bu, const float* __restrict__ ba,
    const int* __restrict__ itp, float* __restrict__ out) {
    __shared__ Smem sm;
    int tid = threadIdx.x, lane = tid & 31, g = tid >> 5;
    int pid = blockIdx.x;
    int b = pid / 196;
    int rem = pid - b * 196;
    int oy = rem / 14;
    int ox = rem - oy * 14;
    char* vcp = reinterpret_cast<char*>(g_vc) + (size_t)pid * VC_BYTES_PER_POS;

    // Patch gather (float4-vectorized): n = (ki*3+kj)*16 + bc
    for (int q = tid; q < 576; q += 256) {
        int n = q >> 2, f = q & 3;
        int bc = n & 15, kk = n >> 4;
        int ki = kk / 3, kj = kk - ki * 3;
        const float4* src = reinterpret_cast<const float4*>(
            x + (((size_t)(b * 16 + oy + ki) * 16 + (ox + kj)) * 16 + bc) * 16);
        reinterpret_cast<float4*>(sm.pose)[q] = __ldg(src + f);
    }
    for (int n = tid; n < NCAP; n += 256) {
        int bc = n & 15, kk = n >> 4;
        int ki = kk / 3, kj = kk - ki * 3;
        sm.a[n] = a[((size_t)(b * 16 + oy + ki) * 16 + (ox + kj)) * 16 + bc];
    }
    __syncthreads();

    int iters = 2;
    if (itp) {
        int iv = __ldg(itp);
        if (iv >= 1 && iv <= 64) {
            iters = iv;
        } else {
            float f = __int_as_float(iv);  // guard against float-encoded scalar
            if (f >= 1.0f && f <= 64.0f) iters = (int)f;
        }
    }

    // iteration 0: uniform responsibilities (also fills the vote cache)
    vote_pass0(sm, vcp, lane, g, tid);
    if (iters == 1) {
        stats<true>(sm, bu, ba, tid);
    } else {
        stats<false>(sm, bu, ba, tid);
        // iterations 1..iters-1: fused E-step (of prev iter) + M-accumulation
        for (int it = 1; it < iters; ++it) {
            vote_passE(sm, vcp, lane, g, tid);
            if (it == iters - 1) stats<true>(sm, bu, ba, tid);
            else stats<false>(sm, bu, ba, tid);
        }
    }

    // outputs: p_out (pid*512 + c*16+p) then a_out (POUT_ELEMS + pid*32 + c)
    float4* pout4 = reinterpret_cast<float4*>(out + (size_t)pid * 512);
    if (tid < 128) {
        int c = tid >> 2, k = tid & 3;
        pout4[tid] = *reinterpret_cast<const float4*>(sm.M1 + c * 20 + k * 4);
    }
    if (tid < 32) out[POUT_ELEMS + pid * 32 + tid] = sm.AO[tid];
}

extern "C" void kernel_launch(void* const* d_in, const int* in_sizes, int n_in,
                              void* d_out, int out_size) {
    const float* x = (const float*)d_in[0];
    const float* a = (const float*)d_in[1];
    const float* w = (const float*)d_in[2];
    const float* bu = (const float*)d_in[3];
    const float* ba = (const float*)d_in[4];
    const int* itp = (n_in >= 6) ? (const int*)d_in[5] : nullptr;
    convert_w_kernel<<<(WHALF_ELEMS / 8 + 255) / 256, 256>>>(w);
    convcaps_kernel<<<NPOS, 256>>>(x, a, bu, ba, itp, (float*)d_out);
}